// round 17
// baseline (speedup 1.0000x reference)
#include <cuda_runtime.h>
#include <cuda_fp16.h>
#include <math.h>
#include <stdint.h>

#define DIM   512
#define NQ    64
#define NB    2048
#define NTOT  32768                 /* N = 512 e * 64 k */
#define NTIL  128                   /* n-tiles (256 n each) */
#define SQRT2 1.4142135623730951f

/* ---- scratch (static device globals; no allocation APIs) ---- */
__device__ __half g_Wh[(size_t)NTOT * DIM];           /* W fp16, [n=(e,k)][d], 32 MB */
__device__ __half g_Ph[(size_t)NB * DIM];             /* P fp16 */
__device__ float  g_pgr[(size_t)NB * NTIL * NQ];      /* grad partials [b][nt][k] */
__device__ float  g_ppg[(size_t)NB * NTIL * NQ];      /* pg partials   [b][nt][k] */
__device__ float  g_nsq_part[DIM * NQ];
__device__ float  g_norm[NQ];

#define SWZ(o) ((o) ^ (((o) >> 3) & 0x70))

__device__ __forceinline__ void cpa16(uint32_t dst, const void* src) {
    asm volatile("cp.async.cg.shared.global [%0], [%1], 16;" :: "r"(dst), "l"(src));
}
__device__ __forceinline__ uint32_t s2u(const void* p) {
    return (uint32_t)__cvta_generic_to_shared(p);
}
__device__ __forceinline__ void ldsm4(uint32_t* r, uint32_t addr) {
    asm volatile("ldmatrix.sync.aligned.m8n8.x4.shared.b16 {%0,%1,%2,%3}, [%4];"
                 : "=r"(r[0]), "=r"(r[1]), "=r"(r[2]), "=r"(r[3]) : "r"(addr));
}
__device__ __forceinline__ void mma16816(float* c, const uint32_t* a, const uint32_t* b) {
    asm volatile(
        "mma.sync.aligned.m16n8k16.row.col.f32.f16.f16.f32 "
        "{%0,%1,%2,%3}, {%4,%5,%6,%7}, {%8,%9}, {%0,%1,%2,%3};"
        : "+f"(c[0]), "+f"(c[1]), "+f"(c[2]), "+f"(c[3])
        : "r"(a[0]), "r"(a[1]), "r"(a[2]), "r"(a[3]), "r"(b[0]), "r"(b[1]));
}

/* ============================================================
 * Kernel 0: convert P to fp16
 * ============================================================ */
__global__ __launch_bounds__(256) void hsq_psplit(const float* __restrict__ points)
{
    for (int i = blockIdx.x * 256 + threadIdx.x; i < NB * DIM; i += gridDim.x * 256)
        g_Ph[i] = __float2half(points[i]);
}

/* ============================================================
 * Kernel 1: build W-fp16 [n=(e,k)][d] + partial norms. 1 blk/e.
 * ============================================================ */
__global__ __launch_bounds__(256) void hsq_prep(const float* __restrict__ q_coefs)
{
    __shared__ float vs[64][65];
    const int e  = blockIdx.x;
    const int t  = threadIdx.x;
    const int k  = t & 63;
    const int ds = t >> 6;
    float nsq = 0.0f;

    for (int d0 = 0; d0 < DIM; d0 += 64) {
        #pragma unroll 4
        for (int it = 0; it < 16; it++) {
            const int d = d0 + it * 4 + ds;
            const int i = d < e ? d : e;
            const int j = d < e ? e : d;
            const int m = i * DIM - (i * (i - 1)) / 2 + (j - i);
            const float qv = q_coefs[(size_t)m * NQ + k];
            vs[it * 4 + ds][k] = qv * ((d == e) ? 2.0f : SQRT2);
            if (d <= e) nsq += qv * qv;
        }
        __syncthreads();
        const int dl = t & 63;
        const int ks = t >> 6;
        #pragma unroll 4
        for (int kk = 0; kk < 16; kk++) {
            const int kq = kk * 4 + ks;
            g_Wh[((size_t)((e << 6) + kq)) * DIM + d0 + dl] = __float2half(vs[dl][kq]);
        }
        __syncthreads();
    }

    __shared__ float red[256];
    red[t] = nsq;
    __syncthreads();
    if (ds == 0)
        g_nsq_part[e * NQ + k] = red[k] + red[64 + k] + red[128 + k] + red[192 + k];
}

/* ============================================================
 * Kernel 2: finalize norms — 64 blocks, deterministic tree
 * ============================================================ */
__global__ __launch_bounds__(256) void hsq_norm(void)
{
    __shared__ float sh[256];
    const int k = blockIdx.x;
    float s = 0.0f;
    for (int e = threadIdx.x; e < DIM; e += 256)
        s += g_nsq_part[e * NQ + k];
    sh[threadIdx.x] = s;
    __syncthreads();
    #pragma unroll
    for (int o = 128; o > 0; o >>= 1) {
        if (threadIdx.x < o) sh[threadIdx.x] += sh[threadIdx.x + o];
        __syncthreads();
    }
    if (threadIdx.x == 0) g_norm[k] = sqrtf(sh[0]);
}

/* ============================================================
 * Kernel 3: GEMM + fused fold epilogue (transpose-then-reduce).
 * CTA 128m x 256n (4 e), 512 thr, warps 4m x 4n (tile 32x64),
 * K = 8 chunks of 64, 4-stage cp.async pipeline (4 x 48 KB).
 * Epilogue: all warps store g = C + l to disjoint smem regions
 * [wn][128][68] in one pass, then threads reduce g^2 / p_e*g
 * across e in registers and write coalesced partials [b][nt][k].
 * ============================================================ */
__global__ __launch_bounds__(512, 1) void hsq_gemm(const float* __restrict__ points,
                                                   const float* __restrict__ l_coefs)
{
    extern __shared__ char sm[];
    const int t  = threadIdx.x;
    const int l  = t & 31;
    const int w  = t >> 5;
    const int wn = w & 3;            /* n-warp: owns one e (64 cols) */
    const int wm = w >> 2;           /* m-warp 0..3 */
    const int b0 = blockIdx.x * 128;
    const int nt = blockIdx.y;
    const int n0 = nt * 256;
    const uint32_t sbase = s2u(sm);

    /* stage: A @0 (16 KB), B @16K (32 KB); stride 48 KB */
    auto load_chunk = [&](int s, int c) {
        const int d0 = c * 64;
        const uint32_t st = sbase + (uint32_t)s * 49152u;
        #pragma unroll
        for (int u = t; u < 1024; u += 512) {
            const int row = u >> 3, sub = u & 7;
            const uint32_t off = SWZ((uint32_t)(row * 128 + sub * 16));
            cpa16(st + off, g_Ph + (size_t)(b0 + row) * DIM + d0 + sub * 8);
        }
        #pragma unroll
        for (int u = t; u < 2048; u += 512) {
            const int row = u >> 3, sub = u & 7;
            const uint32_t off = SWZ((uint32_t)(row * 128 + sub * 16));
            cpa16(st + 16384u + off, g_Wh + (size_t)(n0 + row) * DIM + d0 + sub * 8);
        }
    };

    load_chunk(0, 0);
    asm volatile("cp.async.commit_group;");
    load_chunk(1, 1);
    asm volatile("cp.async.commit_group;");
    load_chunk(2, 2);
    asm volatile("cp.async.commit_group;");

    float C[2][8][4] = {};

    for (int c = 0; c < 8; c++) {
        if (c + 3 < 8) load_chunk((c + 3) & 3, c + 3);
        asm volatile("cp.async.commit_group;");
        asm volatile("cp.async.wait_group 3;");
        __syncthreads();

        const uint32_t st = sbase + (uint32_t)(c & 3) * 49152u;

        #pragma unroll
        for (int kk = 0; kk < 4; kk++) {
            uint32_t ah[2][4];
            #pragma unroll
            for (int mi = 0; mi < 2; mi++) {
                const int row = wm * 32 + mi * 16 + (l & 15);
                const uint32_t kb = (uint32_t)(kk * 32 + ((l >> 4) << 4));
                ldsm4(ah[mi], st + SWZ((uint32_t)(row * 128) + kb));
            }
            uint32_t bh[8][2];
            #pragma unroll
            for (int nj = 0; nj < 4; nj++) {
                const int nrow = wn * 64 + nj * 16 + (l & 7) + ((l >> 4) << 3);
                const uint32_t kb = (uint32_t)(kk * 32 + (((l >> 3) & 1) << 4));
                uint32_t r[4];
                ldsm4(r, st + 16384u + SWZ((uint32_t)(nrow * 128) + kb));
                bh[2 * nj][0] = r[0]; bh[2 * nj][1] = r[1];
                bh[2 * nj + 1][0] = r[2]; bh[2 * nj + 1][1] = r[3];
            }
            #pragma unroll
            for (int mi = 0; mi < 2; mi++)
                #pragma unroll
                for (int nf = 0; nf < 8; nf++)
                    mma16816(C[mi][nf], ah[mi], bh[nf]);
        }
        __syncthreads();
    }

    /* ---- fused fold epilogue: transpose then reduce ---- */
    asm volatile("cp.async.wait_group 0;");
    __syncthreads();

    float* gsm = (float*)sm;                    /* [4 e][128 m][68] = 139264 B */
    float* psh = (float*)(sm + 139264);         /* [128 m][4 e]    =   2048 B */

    /* stage p[m][e'] (each value read 16x later) */
    psh[t] = points[(size_t)(b0 + (t >> 2)) * DIM + nt * 4 + (t & 3)];

    /* store phase: all 16 warps in parallel, disjoint regions */
    {
        const int e  = nt * 4 + wn;
        const int kb = 2 * (l & 3);
        float* greg = gsm + wn * 8704;
        #pragma unroll
        for (int nf = 0; nf < 8; nf++) {
            const float2 lv = *(const float2*)(l_coefs + e * NQ + nf * 8 + kb);
            #pragma unroll
            for (int mi = 0; mi < 2; mi++) {
                const int m0 = wm * 32 + mi * 16 + (l >> 2);
                *(float2*)(greg + m0 * 68 + nf * 8 + kb) =
                    make_float2(C[mi][nf][0] + lv.x, C[mi][nf][1] + lv.y);
                *(float2*)(greg + (m0 + 8) * 68 + nf * 8 + kb) =
                    make_float2(C[mi][nf][2] + lv.x, C[mi][nf][3] + lv.y);
            }
        }
    }
    __syncthreads();

    /* reduce phase: per-thread register reduction across the 4 e */
    {
        const int k4 = (t & 15) * 4;
        #pragma unroll
        for (int iter = 0; iter < 4; iter++) {
            const int m = iter * 32 + (t >> 4);
            float4 gr = make_float4(0.f, 0.f, 0.f, 0.f);
            float4 pg = make_float4(0.f, 0.f, 0.f, 0.f);
            #pragma unroll
            for (int ep = 0; ep < 4; ep++) {
                const float4 g = *(const float4*)(gsm + ep * 8704 + m * 68 + k4);
                const float pe = psh[m * 4 + ep];
                gr.x = fmaf(g.x, g.x, gr.x); gr.y = fmaf(g.y, g.y, gr.y);
                gr.z = fmaf(g.z, g.z, gr.z); gr.w = fmaf(g.w, g.w, gr.w);
                pg.x = fmaf(pe, g.x, pg.x);  pg.y = fmaf(pe, g.y, pg.y);
                pg.z = fmaf(pe, g.z, pg.z);  pg.w = fmaf(pe, g.w, pg.w);
            }
            const size_t o = (size_t)(b0 + m) * (NTIL * NQ) + nt * NQ + k4;
            *(float4*)(g_pgr + o) = gr;
            *(float4*)(g_ppg + o) = pg;
        }
    }
}

/* ============================================================
 * Kernel 4: reduce partials (fixed nt order) + p.l dot + score.
 * CTA: 4 b-rows x 64 k (256 thr).
 * ============================================================ */
__global__ __launch_bounds__(256, 1) void hsq_fold(const float* __restrict__ points,
                                                   const float* __restrict__ l_coefs,
                                                   const float* __restrict__ free_coefs,
                                                   float* __restrict__ out)
{
    extern __shared__ float fs[];
    float* ls  = fs;            /* l_coefs staged: 512 x 64 */
    float* psh = fs + 32768;    /* 4 x 512 p rows */

    const int b0 = blockIdx.x * 4;
    const int t  = threadIdx.x;

    for (int i = t; i < DIM * NQ; i += 256) ls[i] = l_coefs[i];
    for (int i = t; i < 4 * DIM; i += 256)  psh[i] = points[(size_t)b0 * DIM + i];
    __syncthreads();

    const int k  = t & 63;
    const int bi = t >> 6;
    const int b  = b0 + bi;

    float grad = 0.0f, pg = 0.0f;
    const float* gr = g_pgr + (size_t)b * (NTIL * NQ) + k;
    const float* pp = g_ppg + (size_t)b * (NTIL * NQ) + k;
    #pragma unroll 8
    for (int nt = 0; nt < NTIL; nt++) {
        grad += gr[nt << 6];
        pg   += pp[nt << 6];
    }

    float pl = 0.0f;
    #pragma unroll 8
    for (int d = 0; d < DIM; d++)
        pl = fmaf(psh[bi * DIM + d], ls[(d << 6) + k], pl);

    const float nrm    = g_norm[k];
    const float values = fabsf(0.5f * (pg + pl) + free_coefs[k]);
    const float score  = (sqrtf(grad * 0.25f + values * nrm) - 0.5f * sqrtf(grad)) / nrm;
    out[(size_t)b * NQ + k] = score;
}

/* ============================================================ */
extern "C" void kernel_launch(void* const* d_in, const int* in_sizes, int n_in,
                              void* d_out, int out_size)
{
    const float* points = nullptr;
    const float* q      = nullptr;
    const float* l      = nullptr;
    const float* fr     = nullptr;

    for (int i = 0; i < n_in; i++) {
        switch (in_sizes[i]) {
            case NB * DIM:    points = (const float*)d_in[i]; break;
            case 131328 * NQ: q      = (const float*)d_in[i]; break;
            case DIM * NQ:    l      = (const float*)d_in[i]; break;
            case NQ:          fr     = (const float*)d_in[i]; break;
        }
    }
    if (!points) points = (const float*)d_in[0];
    if (!q)      q      = (const float*)d_in[1];
    if (!l)      l      = (const float*)d_in[2];
    if (!fr)     fr     = (const float*)d_in[3];

    cudaFuncSetAttribute(hsq_gemm, cudaFuncAttributeMaxDynamicSharedMemorySize, 196608);
    cudaFuncSetAttribute(hsq_fold, cudaFuncAttributeMaxDynamicSharedMemorySize, 139264);

    hsq_psplit<<<512, 256>>>(points);
    hsq_prep<<<DIM, 256>>>(q);
    hsq_norm<<<64, 256>>>();

    dim3 ggrid(NB / 128, NTOT / 256);           /* (16, 128); x fastest -> B tile L2 reuse */
    hsq_gemm<<<ggrid, 512, 196608>>>(points, l);

    hsq_fold<<<NB / 4, 256, 139264>>>(points, l, fr, (float*)d_out);
}